// round 7
// baseline (speedup 1.0000x reference)
#include <cuda_runtime.h>
#include <cuda_bf16.h>
#include <cstdint>
#include <math.h>

// y[b,y] = softmax_l(U[y].x[b,l]) weighted sum of (F[y].x[b,l]) + fb[y]
// Two GEMMs fused through online (max-free) softmax; bf16 hi/lo 3-product split
// on mma.sync.m16n8k16. Conflict-free smem swizzle, 3-stage cp.async pipeline,
// 2 CTAs/SM. A-side matrices streamed one-at-a-time to stay under 128 regs.

constexpr int Bn = 8, Ln = 2500, Dn = 512, Yn = 8921;
constexpr int TM = 64;                 // labels per CTA
constexpr int TN = 128;                // seq per CTA
constexpr int KC = 32;                 // k per pipeline stage
constexpr int NKC = Dn / KC;           // 16
constexpr int YT = (Yn + TM - 1) / TM; // 140
constexpr int YP = YT * TM;            // 8960
constexpr int NLT = (Ln + TN - 1) / TN;// 20
constexpr int LP = NLT * TN;           // 2560
constexpr int NG = NLT * NKC;          // 320 chunk-stages per CTA
constexpr int OFF_UH = 0, OFF_UL = 4096, OFF_FH = 8192, OFF_FL = 12288;
constexpr int OFF_XH = 16384, OFF_XL = 24576;
constexpr int STAGE = 32768;
constexpr int NST = 3;                 // 96KB dynamic smem -> 2 CTAs/SM

// conflict-free 16B-slot swizzle within a 64B row
__host__ __device__ __forceinline__ int slot_sw(int row, int c) {
    return c ^ (row & 3) ^ ((row >> 2) & 1);
}

// ---------------- pre-split bf16 scratch ----------------
__device__ __align__(16) __nv_bfloat16 g_Uh[(size_t)YP * Dn];
__device__ __align__(16) __nv_bfloat16 g_Ul[(size_t)YP * Dn];
__device__ __align__(16) __nv_bfloat16 g_Fh[(size_t)YP * Dn];
__device__ __align__(16) __nv_bfloat16 g_Fl[(size_t)YP * Dn];
__device__ __align__(16) __nv_bfloat16 g_Xh[(size_t)Bn * LP * Dn];
__device__ __align__(16) __nv_bfloat16 g_Xl[(size_t)Bn * LP * Dn];

// ---------------- asm helpers ----------------
__device__ __forceinline__ void cpa16(uint32_t dst, const void* src) {
    asm volatile("cp.async.cg.shared.global [%0], [%1], 16;" :: "r"(dst), "l"(src));
}
__device__ __forceinline__ void cp_commit() {
    asm volatile("cp.async.commit_group;" ::: "memory");
}
template <int N>
__device__ __forceinline__ void cp_wait() {
    asm volatile("cp.async.wait_group %0;" :: "n"(N) : "memory");
}
__device__ __forceinline__ void ldm4(uint32_t& r0, uint32_t& r1, uint32_t& r2, uint32_t& r3, uint32_t a) {
    asm volatile("ldmatrix.sync.aligned.m8n8.x4.shared.b16 {%0,%1,%2,%3}, [%4];"
        : "=r"(r0), "=r"(r1), "=r"(r2), "=r"(r3) : "r"(a));
}
#define MMA_BF16(d, a, bfr)                                                          \
    asm volatile("mma.sync.aligned.m16n8k16.row.col.f32.bf16.bf16.f32 "              \
        "{%0,%1,%2,%3},{%4,%5,%6,%7},{%8,%9},{%0,%1,%2,%3};"                         \
        : "+f"((d)[0]), "+f"((d)[1]), "+f"((d)[2]), "+f"((d)[3])                     \
        : "r"((a)[0]), "r"((a)[1]), "r"((a)[2]), "r"((a)[3]), "r"((bfr)[0]), "r"((bfr)[1]))

// ---------------- prep: fp32 -> bf16 hi/lo, padded row-major ----------------
__global__ __launch_bounds__(256) void prep_UF(const float* __restrict__ U, const float* __restrict__ F) {
    for (size_t idx = (size_t)blockIdx.x * blockDim.x + threadIdx.x;
         idx < (size_t)YP * Dn; idx += (size_t)gridDim.x * blockDim.x) {
        int y = (int)(idx >> 9);
        float u = 0.f, f = 0.f;
        if (y < Yn) { u = U[idx]; f = F[idx]; }
        __nv_bfloat16 uh = __float2bfloat16(u);
        __nv_bfloat16 ul = __float2bfloat16(u - __bfloat162float(uh));
        __nv_bfloat16 fh = __float2bfloat16(f);
        __nv_bfloat16 fl = __float2bfloat16(f - __bfloat162float(fh));
        g_Uh[idx] = uh; g_Ul[idx] = ul; g_Fh[idx] = fh; g_Fl[idx] = fl;
    }
}
__global__ __launch_bounds__(256) void prep_x(const float* __restrict__ x) {
    for (size_t idx = (size_t)blockIdx.x * blockDim.x + threadIdx.x;
         idx < (size_t)Bn * LP * Dn; idx += (size_t)gridDim.x * blockDim.x) {
        size_t bl = idx >> 9;
        int l = (int)(bl % LP);
        int b = (int)(bl / LP);
        int d = (int)(idx & 511);
        float v = 0.f;
        if (l < Ln) v = x[((size_t)b * Ln + l) * Dn + d];
        __nv_bfloat16 vh = __float2bfloat16(v);
        __nv_bfloat16 vl = __float2bfloat16(v - __bfloat162float(vh));
        g_Xh[idx] = vh; g_Xl[idx] = vl;
    }
}

// ---------------- main fused kernel ----------------
__global__ __launch_bounds__(256, 2)
void attn_main(const float* __restrict__ fb, float* __restrict__ out) {
    extern __shared__ __align__(128) char smem[];
    uint32_t sbase;
    asm("{ .reg .u64 t; cvta.to.shared.u64 t, %1; cvt.u32.u64 %0, t; }" : "=r"(sbase) : "l"(smem));

    const int tid = threadIdx.x;
    const int wid = tid >> 5, lane = tid & 31;
    const int wm = wid >> 2, wn = wid & 3;       // warp grid 2(M) x 4(N)
    const int yt = blockIdx.x, b = blockIdx.y;

    // ---- loader mapping: 8 x 16B cp.async per thread per stage ----
    const int lrow = tid >> 2;                  // 0..63
    const int lc   = tid & 3;                   // 16B chunk in 64B row
    const uint32_t dstA = (uint32_t)lrow * 64 + (uint32_t)(slot_sw(lrow, lc) << 4);
    const size_t a_src = ((size_t)(yt * TM + lrow)) * Dn + lc * 8;
    const size_t x_src = ((size_t)b * LP + lrow) * Dn + lc * 8;

    auto issue = [&](int gi) {
        const int ci = gi & 15, lti = gi >> 4;
        const uint32_t sb = sbase + (uint32_t)(gi % NST) * STAGE;
        const size_t ao = a_src + (size_t)ci * KC;
        cpa16(sb + OFF_UH + dstA, g_Uh + ao);
        cpa16(sb + OFF_UL + dstA, g_Ul + ao);
        cpa16(sb + OFF_FH + dstA, g_Fh + ao);
        cpa16(sb + OFF_FL + dstA, g_Fl + ao);
        const size_t xo = x_src + (size_t)lti * TN * Dn + (size_t)ci * KC;
        cpa16(sb + OFF_XH + dstA,        g_Xh + xo);
        cpa16(sb + OFF_XH + dstA + 4096, g_Xh + xo + (size_t)64 * Dn);
        cpa16(sb + OFF_XL + dstA,        g_Xl + xo);
        cpa16(sb + OFF_XL + dstA + 4096, g_Xl + xo + (size_t)64 * Dn);
    };

    // ---- ldmatrix per-thread invariants ----
    const int lg = lane >> 3, lr = lane & 7;
    const int rA0 = wm * 32 + lr + (lg & 1) * 8;        // A: grp bit0 = row half, bit1 = k half
    const int cA = lg >> 1;
    const int rB0 = wn * 32 + lr + (lg >> 1) * 8;       // B: grp bit1 = n half, bit0 = k half
    const int cB = lg & 1;

    // hoisted intra-stage ldmatrix offsets [kk][mt or bt]
    uint32_t offA[2][2], offB[2][2];
    #pragma unroll
    for (int kk = 0; kk < 2; kk++) {
        #pragma unroll
        for (int t2 = 0; t2 < 2; t2++) {
            const int ra = rA0 + t2 * 16;
            offA[kk][t2] = (uint32_t)ra * 64 + (uint32_t)(slot_sw(ra, kk * 2 + cA) << 4);
            const int rb = rB0 + t2 * 16;
            offB[kk][t2] = (uint32_t)rb * 64 + (uint32_t)(slot_sw(rb, kk * 2 + cB) << 4);
        }
    }

    const int quad = lane >> 2, tc = lane & 3;

    float z[4] = {0.f, 0.f, 0.f, 0.f}, nw[4] = {0.f, 0.f, 0.f, 0.f};

    // prologue: 2 stages in flight (3-buffer ring)
    issue(0); cp_commit();
    issue(1); cp_commit();

    for (int lt = 0; lt < NLT; lt++) {
        float accS[2][4][4], accT[2][4][4];
        #pragma unroll
        for (int mt = 0; mt < 2; mt++)
            #pragma unroll
            for (int nt = 0; nt < 4; nt++)
                #pragma unroll
                for (int j = 0; j < 4; j++) { accS[mt][nt][j] = 0.f; accT[mt][nt][j] = 0.f; }

        for (int c = 0; c < NKC; c++) {
            const int g = lt * NKC + c;
            cp_wait<1>();
            __syncthreads();
            const int gi = g + 2;
            if (gi < NG) issue(gi);
            cp_commit();

            const uint32_t sb = sbase + (uint32_t)(g % NST) * STAGE;
            #pragma unroll
            for (int kk = 0; kk < 2; kk++) {
                uint32_t XH[4][2], XL[4][2], A[2][4];
                #pragma unroll
                for (int bt = 0; bt < 2; bt++) {
                    ldm4(XH[bt*2][0], XH[bt*2][1], XH[bt*2+1][0], XH[bt*2+1][1], sb + OFF_XH + offB[kk][bt]);
                    ldm4(XL[bt*2][0], XL[bt*2][1], XL[bt*2+1][0], XL[bt*2+1][1], sb + OFF_XL + offB[kk][bt]);
                }
                // --- AH: S += AH*XH, S += AH*XL ---
                #pragma unroll
                for (int mt = 0; mt < 2; mt++)
                    ldm4(A[mt][0], A[mt][1], A[mt][2], A[mt][3], sb + OFF_UH + offA[kk][mt]);
                #pragma unroll
                for (int mt = 0; mt < 2; mt++)
                    #pragma unroll
                    for (int nt = 0; nt < 4; nt++) {
                        MMA_BF16(accS[mt][nt], A[mt], XH[nt]);
                        MMA_BF16(accS[mt][nt], A[mt], XL[nt]);
                    }
                // --- AL: S += AL*XH ---
                #pragma unroll
                for (int mt = 0; mt < 2; mt++)
                    ldm4(A[mt][0], A[mt][1], A[mt][2], A[mt][3], sb + OFF_UL + offA[kk][mt]);
                #pragma unroll
                for (int mt = 0; mt < 2; mt++)
                    #pragma unroll
                    for (int nt = 0; nt < 4; nt++)
                        MMA_BF16(accS[mt][nt], A[mt], XH[nt]);
                // --- FH: T += FH*XH, T += FH*XL ---
                #pragma unroll
                for (int mt = 0; mt < 2; mt++)
                    ldm4(A[mt][0], A[mt][1], A[mt][2], A[mt][3], sb + OFF_FH + offA[kk][mt]);
                #pragma unroll
                for (int mt = 0; mt < 2; mt++)
                    #pragma unroll
                    for (int nt = 0; nt < 4; nt++) {
                        MMA_BF16(accT[mt][nt], A[mt], XH[nt]);
                        MMA_BF16(accT[mt][nt], A[mt], XL[nt]);
                    }
                // --- FL: T += FL*XH ---
                #pragma unroll
                for (int mt = 0; mt < 2; mt++)
                    ldm4(A[mt][0], A[mt][1], A[mt][2], A[mt][3], sb + OFF_FL + offA[kk][mt]);
                #pragma unroll
                for (int mt = 0; mt < 2; mt++)
                    #pragma unroll
                    for (int nt = 0; nt < 4; nt++)
                        MMA_BF16(accT[mt][nt], A[mt], XH[nt]);
            }
        }

        // max-free softmax partial update (scores bounded ~|2|)
        #pragma unroll
        for (int nt = 0; nt < 4; nt++)
            #pragma unroll
            for (int j = 0; j < 4; j++) {
                const int p = j & 1;
                const int l = lt * TN + wn * 32 + nt * 8 + tc * 2 + p;
                const bool v = (l < Ln);
                #pragma unroll
                for (int mt = 0; mt < 2; mt++) {
                    const int zi = mt * 2 + (j >> 1);
                    const float e = v ? __expf(accS[mt][nt][j]) : 0.f;
                    z[zi] += e;
                    nw[zi] = fmaf(e, accT[mt][nt][j], nw[zi]);
                }
            }
    }

    // ---- final reduction ----
    cp_wait<0>();
    __syncthreads();
    #pragma unroll
    for (int zi = 0; zi < 4; zi++) {
        z[zi]  += __shfl_xor_sync(0xffffffffu, z[zi], 1);
        z[zi]  += __shfl_xor_sync(0xffffffffu, z[zi], 2);
        nw[zi] += __shfl_xor_sync(0xffffffffu, nw[zi], 1);
        nw[zi] += __shfl_xor_sync(0xffffffffu, nw[zi], 2);
    }
    float2* red = (float2*)smem;   // [4 warp_n][64 rows]
    if (tc == 0) {
        #pragma unroll
        for (int zi = 0; zi < 4; zi++) {
            const int mt = zi >> 1, rh = zi & 1;
            const int row = wm * 32 + mt * 16 + rh * 8 + quad;
            red[wn * 64 + row] = make_float2(z[zi], nw[zi]);
        }
    }
    __syncthreads();
    if (tid < 64) {
        float zz = 0.f, nn = 0.f;
        #pragma unroll
        for (int w = 0; w < 4; w++) { float2 v = red[w * 64 + tid]; zz += v.x; nn += v.y; }
        const int y = yt * TM + tid;
        if (y < Yn) out[(size_t)b * Yn + y] = nn / zz + fb[y];
    }
}

// ---------------- host launch ----------------
extern "C" void kernel_launch(void* const* d_in, const int* in_sizes, int n_in,
                              void* d_out, int out_size) {
    const float* x  = (const float*)d_in[0];
    const float* Uw = (const float*)d_in[1];
    const float* Fw = (const float*)d_in[2];
    const float* fb = (const float*)d_in[3];
    float* out = (float*)d_out;
    (void)in_sizes; (void)n_in; (void)out_size;

    prep_UF<<<2048, 256>>>(Uw, Fw);
    prep_x<<<2048, 256>>>(x);

    cudaFuncSetAttribute(attn_main, cudaFuncAttributeMaxDynamicSharedMemorySize, NST * STAGE);
    attn_main<<<dim3(YT, Bn), 256, NST * STAGE>>>(fb, out);
}

// round 8
// speedup vs baseline: 1.0603x; 1.0603x over previous
#include <cuda_runtime.h>
#include <cuda_bf16.h>
#include <cstdint>
#include <math.h>

// y[b,y] = softmax_l(U[y].x[b,l]) weighted sum of (F[y].x[b,l]) + fb[y]
// Two GEMMs fused through online (max-free) softmax; bf16 hi/lo 3-product split
// on mma.sync.m16n8k16. Conflict-free smem swizzle, 3-stage cp.async pipeline,
// 2 CTAs/SM. Half-split mainloop: {U-side -> S}, then {F-side -> T} reusing
// the A fragment registers (no spills, 24-MMA cover per LDSM batch).

constexpr int Bn = 8, Ln = 2500, Dn = 512, Yn = 8921;
constexpr int TM = 64;                 // labels per CTA
constexpr int TN = 128;                // seq per CTA
constexpr int KC = 32;                 // k per pipeline stage
constexpr int NKC = Dn / KC;           // 16
constexpr int YT = (Yn + TM - 1) / TM; // 140
constexpr int YP = YT * TM;            // 8960
constexpr int NLT = (Ln + TN - 1) / TN;// 20
constexpr int LP = NLT * TN;           // 2560
constexpr int NG = NLT * NKC;          // 320 chunk-stages per CTA
constexpr int OFF_UH = 0, OFF_UL = 4096, OFF_FH = 8192, OFF_FL = 12288;
constexpr int OFF_XH = 16384, OFF_XL = 24576;
constexpr int STAGE = 32768;
constexpr int NST = 3;                 // 96KB dynamic smem -> 2 CTAs/SM

// conflict-free 16B-slot swizzle within a 64B row
__host__ __device__ __forceinline__ int slot_sw(int row, int c) {
    return c ^ (row & 3) ^ ((row >> 2) & 1);
}

// ---------------- pre-split bf16 scratch ----------------
__device__ __align__(16) __nv_bfloat16 g_Uh[(size_t)YP * Dn];
__device__ __align__(16) __nv_bfloat16 g_Ul[(size_t)YP * Dn];
__device__ __align__(16) __nv_bfloat16 g_Fh[(size_t)YP * Dn];
__device__ __align__(16) __nv_bfloat16 g_Fl[(size_t)YP * Dn];
__device__ __align__(16) __nv_bfloat16 g_Xh[(size_t)Bn * LP * Dn];
__device__ __align__(16) __nv_bfloat16 g_Xl[(size_t)Bn * LP * Dn];

// ---------------- asm helpers ----------------
__device__ __forceinline__ void cpa16(uint32_t dst, const void* src) {
    asm volatile("cp.async.cg.shared.global [%0], [%1], 16;" :: "r"(dst), "l"(src));
}
__device__ __forceinline__ void cp_commit() {
    asm volatile("cp.async.commit_group;" ::: "memory");
}
template <int N>
__device__ __forceinline__ void cp_wait() {
    asm volatile("cp.async.wait_group %0;" :: "n"(N) : "memory");
}
__device__ __forceinline__ void ldm4(uint32_t& r0, uint32_t& r1, uint32_t& r2, uint32_t& r3, uint32_t a) {
    asm volatile("ldmatrix.sync.aligned.m8n8.x4.shared.b16 {%0,%1,%2,%3}, [%4];"
        : "=r"(r0), "=r"(r1), "=r"(r2), "=r"(r3) : "r"(a));
}
#define MMA_BF16(d, a, bfr)                                                          \
    asm volatile("mma.sync.aligned.m16n8k16.row.col.f32.bf16.bf16.f32 "              \
        "{%0,%1,%2,%3},{%4,%5,%6,%7},{%8,%9},{%0,%1,%2,%3};"                         \
        : "+f"((d)[0]), "+f"((d)[1]), "+f"((d)[2]), "+f"((d)[3])                     \
        : "r"((a)[0]), "r"((a)[1]), "r"((a)[2]), "r"((a)[3]), "r"((bfr)[0]), "r"((bfr)[1]))

// ---------------- fused prep: fp32 -> bf16 hi/lo for U, F, x ----------------
// One kernel so the launch sequence is (prep, attn) per call: ncu -s 5 lands on attn_main.
constexpr size_t UF_ELEMS = (size_t)YP * Dn;          // 4,587,520
constexpr size_t X_ELEMS  = (size_t)Bn * LP * Dn;     // 10,485,760
__global__ __launch_bounds__(256) void prep_all(const float* __restrict__ U,
                                                const float* __restrict__ F,
                                                const float* __restrict__ x) {
    const size_t stride = (size_t)gridDim.x * blockDim.x;
    for (size_t idx = (size_t)blockIdx.x * blockDim.x + threadIdx.x;
         idx < UF_ELEMS + X_ELEMS; idx += stride) {
        if (idx < UF_ELEMS) {
            int y = (int)(idx >> 9);
            float u = 0.f, f = 0.f;
            if (y < Yn) { u = U[idx]; f = F[idx]; }
            __nv_bfloat16 uh = __float2bfloat16(u);
            __nv_bfloat16 ul = __float2bfloat16(u - __bfloat162float(uh));
            __nv_bfloat16 fh = __float2bfloat16(f);
            __nv_bfloat16 fl = __float2bfloat16(f - __bfloat162float(fh));
            g_Uh[idx] = uh; g_Ul[idx] = ul; g_Fh[idx] = fh; g_Fl[idx] = fl;
        } else {
            size_t xi = idx - UF_ELEMS;
            size_t bl = xi >> 9;
            int l = (int)(bl % LP);
            int b = (int)(bl / LP);
            int d = (int)(xi & 511);
            float v = 0.f;
            if (l < Ln) v = x[((size_t)b * Ln + l) * Dn + d];
            __nv_bfloat16 vh = __float2bfloat16(v);
            __nv_bfloat16 vl = __float2bfloat16(v - __bfloat162float(vh));
            g_Xh[xi] = vh; g_Xl[xi] = vl;
        }
    }
}

// ---------------- main fused kernel ----------------
__global__ __launch_bounds__(256, 2)
void attn_main(const float* __restrict__ fb, float* __restrict__ out) {
    extern __shared__ __align__(128) char smem[];
    uint32_t sbase;
    asm("{ .reg .u64 t; cvta.to.shared.u64 t, %1; cvt.u32.u64 %0, t; }" : "=r"(sbase) : "l"(smem));

    const int tid = threadIdx.x;
    const int wid = tid >> 5, lane = tid & 31;
    const int wm = wid >> 2, wn = wid & 3;       // warp grid 2(M) x 4(N)
    const int yt = blockIdx.x, b = blockIdx.y;

    // ---- loader mapping: 8 x 16B cp.async per thread per stage ----
    const int lrow = tid >> 2;                  // 0..63
    const int lc   = tid & 3;                   // 16B chunk in 64B row
    const uint32_t dstA = (uint32_t)lrow * 64 + (uint32_t)(slot_sw(lrow, lc) << 4);
    const size_t a_src = ((size_t)(yt * TM + lrow)) * Dn + lc * 8;
    const size_t x_src = ((size_t)b * LP + lrow) * Dn + lc * 8;

    auto issue = [&](int gi) {
        const int ci = gi & 15, lti = gi >> 4;
        const uint32_t sb = sbase + (uint32_t)(gi % NST) * STAGE;
        const size_t ao = a_src + (size_t)ci * KC;
        cpa16(sb + OFF_UH + dstA, g_Uh + ao);
        cpa16(sb + OFF_UL + dstA, g_Ul + ao);
        cpa16(sb + OFF_FH + dstA, g_Fh + ao);
        cpa16(sb + OFF_FL + dstA, g_Fl + ao);
        const size_t xo = x_src + (size_t)lti * TN * Dn + (size_t)ci * KC;
        cpa16(sb + OFF_XH + dstA,        g_Xh + xo);
        cpa16(sb + OFF_XH + dstA + 4096, g_Xh + xo + (size_t)64 * Dn);
        cpa16(sb + OFF_XL + dstA,        g_Xl + xo);
        cpa16(sb + OFF_XL + dstA + 4096, g_Xl + xo + (size_t)64 * Dn);
    };

    // ---- ldmatrix per-thread invariants ----
    const int lg = lane >> 3, lr = lane & 7;
    const int rA0 = wm * 32 + lr + (lg & 1) * 8;        // A: grp bit0 = row half, bit1 = k half
    const int cA = lg >> 1;
    const int rB0 = wn * 32 + lr + (lg >> 1) * 8;       // B: grp bit1 = n half, bit0 = k half
    const int cB = lg & 1;

    // hoisted intra-stage ldmatrix offsets [kk][mt or bt]
    uint32_t offA[2][2], offB[2][2];
    #pragma unroll
    for (int kk = 0; kk < 2; kk++) {
        #pragma unroll
        for (int t2 = 0; t2 < 2; t2++) {
            const int ra = rA0 + t2 * 16;
            offA[kk][t2] = (uint32_t)ra * 64 + (uint32_t)(slot_sw(ra, kk * 2 + cA) << 4);
            const int rb = rB0 + t2 * 16;
            offB[kk][t2] = (uint32_t)rb * 64 + (uint32_t)(slot_sw(rb, kk * 2 + cB) << 4);
        }
    }

    const int quad = lane >> 2, tc = lane & 3;

    float z[4] = {0.f, 0.f, 0.f, 0.f}, nw[4] = {0.f, 0.f, 0.f, 0.f};

    // prologue: 2 stages in flight (3-buffer ring)
    issue(0); cp_commit();
    issue(1); cp_commit();

    for (int lt = 0; lt < NLT; lt++) {
        float accS[2][4][4], accT[2][4][4];
        #pragma unroll
        for (int mt = 0; mt < 2; mt++)
            #pragma unroll
            for (int nt = 0; nt < 4; nt++)
                #pragma unroll
                for (int j = 0; j < 4; j++) { accS[mt][nt][j] = 0.f; accT[mt][nt][j] = 0.f; }

        for (int c = 0; c < NKC; c++) {
            const int g = lt * NKC + c;
            cp_wait<1>();
            __syncthreads();
            const int gi = g + 2;
            if (gi < NG) issue(gi);
            cp_commit();

            const uint32_t sb = sbase + (uint32_t)(g % NST) * STAGE;
            #pragma unroll
            for (int kk = 0; kk < 2; kk++) {
                uint32_t XH[4][2], XL[4][2], A0[2][4], A1[2][4];
                #pragma unroll
                for (int bt = 0; bt < 2; bt++) {
                    ldm4(XH[bt*2][0], XH[bt*2][1], XH[bt*2+1][0], XH[bt*2+1][1], sb + OFF_XH + offB[kk][bt]);
                    ldm4(XL[bt*2][0], XL[bt*2][1], XL[bt*2+1][0], XL[bt*2+1][1], sb + OFF_XL + offB[kk][bt]);
                }
                // ---- half 1: U-side -> S (24 MMAs over 4 LDSMs) ----
                #pragma unroll
                for (int mt = 0; mt < 2; mt++) {
                    ldm4(A0[mt][0], A0[mt][1], A0[mt][2], A0[mt][3], sb + OFF_UH + offA[kk][mt]);
                    ldm4(A1[mt][0], A1[mt][1], A1[mt][2], A1[mt][3], sb + OFF_UL + offA[kk][mt]);
                }
                #pragma unroll
                for (int mt = 0; mt < 2; mt++)
                    #pragma unroll
                    for (int nt = 0; nt < 4; nt++) {
                        MMA_BF16(accS[mt][nt], A0[mt], XH[nt]);
                        MMA_BF16(accS[mt][nt], A0[mt], XL[nt]);
                        MMA_BF16(accS[mt][nt], A1[mt], XH[nt]);
                    }
                // ---- half 2: F-side -> T (reuse A regs) ----
                #pragma unroll
                for (int mt = 0; mt < 2; mt++) {
                    ldm4(A0[mt][0], A0[mt][1], A0[mt][2], A0[mt][3], sb + OFF_FH + offA[kk][mt]);
                    ldm4(A1[mt][0], A1[mt][1], A1[mt][2], A1[mt][3], sb + OFF_FL + offA[kk][mt]);
                }
                #pragma unroll
                for (int mt = 0; mt < 2; mt++)
                    #pragma unroll
                    for (int nt = 0; nt < 4; nt++) {
                        MMA_BF16(accT[mt][nt], A0[mt], XH[nt]);
                        MMA_BF16(accT[mt][nt], A0[mt], XL[nt]);
                        MMA_BF16(accT[mt][nt], A1[mt], XH[nt]);
                    }
            }
        }

        // max-free softmax partial update (scores bounded ~|2|)
        #pragma unroll
        for (int nt = 0; nt < 4; nt++)
            #pragma unroll
            for (int j = 0; j < 4; j++) {
                const int p = j & 1;
                const int l = lt * TN + wn * 32 + nt * 8 + tc * 2 + p;
                const bool v = (l < Ln);
                #pragma unroll
                for (int mt = 0; mt < 2; mt++) {
                    const int zi = mt * 2 + (j >> 1);
                    const float e = v ? __expf(accS[mt][nt][j]) : 0.f;
                    z[zi] += e;
                    nw[zi] = fmaf(e, accT[mt][nt][j], nw[zi]);
                }
            }
    }

    // ---- final reduction ----
    cp_wait<0>();
    __syncthreads();
    #pragma unroll
    for (int zi = 0; zi < 4; zi++) {
        z[zi]  += __shfl_xor_sync(0xffffffffu, z[zi], 1);
        z[zi]  += __shfl_xor_sync(0xffffffffu, z[zi], 2);
        nw[zi] += __shfl_xor_sync(0xffffffffu, nw[zi], 1);
        nw[zi] += __shfl_xor_sync(0xffffffffu, nw[zi], 2);
    }
    float2* red = (float2*)smem;   // [4 warp_n][64 rows]
    if (tc == 0) {
        #pragma unroll
        for (int zi = 0; zi < 4; zi++) {
            const int mt = zi >> 1, rh = zi & 1;
            const int row = wm * 32 + mt * 16 + rh * 8 + quad;
            red[wn * 64 + row] = make_float2(z[zi], nw[zi]);
        }
    }
    __syncthreads();
    if (tid < 64) {
        float zz = 0.f, nn = 0.f;
        #pragma unroll
        for (int w = 0; w < 4; w++) { float2 v = red[w * 64 + tid]; zz += v.x; nn += v.y; }
        const int y = yt * TM + tid;
        if (y < Yn) out[(size_t)b * Yn + y] = nn / zz + fb[y];
    }
}

// ---------------- host launch ----------------
extern "C" void kernel_launch(void* const* d_in, const int* in_sizes, int n_in,
                              void* d_out, int out_size) {
    const float* x  = (const float*)d_in[0];
    const float* Uw = (const float*)d_in[1];
    const float* Fw = (const float*)d_in[2];
    const float* fb = (const float*)d_in[3];
    float* out = (float*)d_out;
    (void)in_sizes; (void)n_in; (void)out_size;

    prep_all<<<4096, 256>>>(Uw, Fw, x);

    cudaFuncSetAttribute(attn_main, cudaFuncAttributeMaxDynamicSharedMemorySize, NST * STAGE);
    attn_main<<<dim3(YT, Bn), 256, NST * STAGE>>>(fb, out);
}

// round 9
// speedup vs baseline: 2.8779x; 2.7141x over previous
#include <cuda_runtime.h>
#include <cuda_fp16.h>
#include <cstdint>
#include <math.h>

// y[b,y] = softmax_l(U[y].x[b,l]) weighted sum of (F[y].x[b,l]) + fb[y]
// Two GEMMs fused through online (max-free) softmax. Pure fp16 operands
// (no hi/lo split): fp16 11-bit mantissa keeps end-to-end rel err ~2e-4
// (averaging through softmax kills per-term quantization noise).
// mma.sync.m16n8k16.f32.f16.f16.f32, KC=64 stages, 3-stage cp.async ring,
// conflict-free 128B-row swizzle, 2 CTAs/SM.

constexpr int Bn = 8, Ln = 2500, Dn = 512, Yn = 8921;
constexpr int TM = 64;                 // labels per CTA
constexpr int TN = 128;                // seq per CTA
constexpr int KC = 64;                 // k per pipeline stage
constexpr int NKC = Dn / KC;           // 8
constexpr int YT = (Yn + TM - 1) / TM; // 140
constexpr int YP = YT * TM;            // 8960
constexpr int NLT = (Ln + TN - 1) / TN;// 20
constexpr int LP = NLT * TN;           // 2560
constexpr int NG = NLT * NKC;          // 160 chunk-stages per CTA
// stage layout: U 64x64 fp16 (8KB), F (8KB), X 128x64 fp16 (16KB) = 32KB
constexpr int OFF_U = 0, OFF_F = 8192, OFF_X = 16384;
constexpr int STAGE = 32768;
constexpr int NST = 3;                 // 96KB dynamic smem -> 2 CTAs/SM

// conflict-free 16B-slot swizzle within a 128B row (8 slots)
__host__ __device__ __forceinline__ int slot_sw(int row, int c) {
    return c ^ (row & 7);
}

// ---------------- fp16 scratch ----------------
__device__ __align__(16) __half g_U[(size_t)YP * Dn];
__device__ __align__(16) __half g_F[(size_t)YP * Dn];
__device__ __align__(16) __half g_X[(size_t)Bn * LP * Dn];

// ---------------- asm helpers ----------------
__device__ __forceinline__ void cpa16(uint32_t dst, const void* src) {
    asm volatile("cp.async.cg.shared.global [%0], [%1], 16;" :: "r"(dst), "l"(src));
}
__device__ __forceinline__ void cp_commit() {
    asm volatile("cp.async.commit_group;" ::: "memory");
}
template <int N>
__device__ __forceinline__ void cp_wait() {
    asm volatile("cp.async.wait_group %0;" :: "n"(N) : "memory");
}
__device__ __forceinline__ void ldm4(uint32_t& r0, uint32_t& r1, uint32_t& r2, uint32_t& r3, uint32_t a) {
    asm volatile("ldmatrix.sync.aligned.m8n8.x4.shared.b16 {%0,%1,%2,%3}, [%4];"
        : "=r"(r0), "=r"(r1), "=r"(r2), "=r"(r3) : "r"(a));
}
#define MMA_F16(d, a, bfr)                                                           \
    asm volatile("mma.sync.aligned.m16n8k16.row.col.f32.f16.f16.f32 "                \
        "{%0,%1,%2,%3},{%4,%5,%6,%7},{%8,%9},{%0,%1,%2,%3};"                         \
        : "+f"((d)[0]), "+f"((d)[1]), "+f"((d)[2]), "+f"((d)[3])                     \
        : "r"((a)[0]), "r"((a)[1]), "r"((a)[2]), "r"((a)[3]), "r"((bfr)[0]), "r"((bfr)[1]))

// ---------------- fused prep: fp32 -> fp16 for U, F, x ----------------
constexpr size_t UF_ELEMS = (size_t)YP * Dn;          // 4,587,520
constexpr size_t X_ELEMS  = (size_t)Bn * LP * Dn;     // 10,485,760
__global__ __launch_bounds__(256) void prep_all(const float* __restrict__ U,
                                                const float* __restrict__ F,
                                                const float* __restrict__ x) {
    const size_t stride = (size_t)gridDim.x * blockDim.x;
    for (size_t idx = (size_t)blockIdx.x * blockDim.x + threadIdx.x;
         idx < UF_ELEMS + X_ELEMS; idx += stride) {
        if (idx < UF_ELEMS) {
            int y = (int)(idx >> 9);
            float u = 0.f, f = 0.f;
            if (y < Yn) { u = U[idx]; f = F[idx]; }
            g_U[idx] = __float2half_rn(u);
            g_F[idx] = __float2half_rn(f);
        } else {
            size_t xi = idx - UF_ELEMS;
            size_t bl = xi >> 9;
            int l = (int)(bl % LP);
            int b = (int)(bl / LP);
            int d = (int)(xi & 511);
            float v = 0.f;
            if (l < Ln) v = x[((size_t)b * Ln + l) * Dn + d];
            g_X[xi] = __float2half_rn(v);
        }
    }
}

// ---------------- main fused kernel ----------------
__global__ __launch_bounds__(256, 2)
void attn_main(const float* __restrict__ fb, float* __restrict__ out) {
    extern __shared__ __align__(128) char smem[];
    uint32_t sbase;
    asm("{ .reg .u64 t; cvta.to.shared.u64 t, %1; cvt.u32.u64 %0, t; }" : "=r"(sbase) : "l"(smem));

    const int tid = threadIdx.x;
    const int wid = tid >> 5, lane = tid & 31;
    const int wm = wid >> 2, wn = wid & 3;       // warp grid 2(M) x 4(N)
    const int yt = blockIdx.x, b = blockIdx.y;

    // ---- loader mapping: 8 threads per 128B row; quarter-warp = 8 distinct slots ----
    const int lr0 = tid >> 3;                   // 0..31
    const int lcc = tid & 7;                    // 16B chunk in 128B row

    auto issue = [&](int gi) {
        const int ci = gi & 7, lti = gi >> 3;
        const uint32_t sb = sbase + (uint32_t)(gi % NST) * STAGE;
        #pragma unroll
        for (int rr = 0; rr < 2; rr++) {
            const int row = lr0 + rr * 32;
            const uint32_t d = (uint32_t)row * 128 + (uint32_t)(slot_sw(row, lcc) << 4);
            const size_t s = ((size_t)(yt * TM + row)) * Dn + (size_t)ci * KC + lcc * 8;
            cpa16(sb + OFF_U + d, g_U + s);
            cpa16(sb + OFF_F + d, g_F + s);
        }
        #pragma unroll
        for (int rr = 0; rr < 4; rr++) {
            const int row = lr0 + rr * 32;
            const uint32_t d = (uint32_t)row * 128 + (uint32_t)(slot_sw(row, lcc) << 4);
            const size_t s = ((size_t)b * LP + (size_t)lti * TN + row) * Dn + (size_t)ci * KC + lcc * 8;
            cpa16(sb + OFF_X + d, g_X + s);
        }
    };

    // ---- ldmatrix per-thread invariants ----
    const int lg = lane >> 3, lr = lane & 7;
    const int rA0 = wm * 32 + lr + (lg & 1) * 8;        // A: grp bit0 = row half, bit1 = k half
    const int cA = lg >> 1;
    const int rB0 = wn * 32 + lr + (lg >> 1) * 8;       // B: grp bit1 = n half, bit0 = k half
    const int cB = lg & 1;

    // hoisted intra-stage ldmatrix offsets [kk][mt or bt], kk = k16 step in KC=64
    uint32_t offA[4][2], offB[4][2];
    #pragma unroll
    for (int kk = 0; kk < 4; kk++) {
        #pragma unroll
        for (int t2 = 0; t2 < 2; t2++) {
            const int ra = rA0 + t2 * 16;
            offA[kk][t2] = (uint32_t)ra * 128 + (uint32_t)(slot_sw(ra, kk * 2 + cA) << 4);
            const int rb = rB0 + t2 * 16;
            offB[kk][t2] = (uint32_t)rb * 128 + (uint32_t)(slot_sw(rb, kk * 2 + cB) << 4);
        }
    }

    const int quad = lane >> 2, tc = lane & 3;

    float z[4] = {0.f, 0.f, 0.f, 0.f}, nw[4] = {0.f, 0.f, 0.f, 0.f};

    // prologue: 2 stages in flight (3-buffer ring)
    issue(0); cp_commit();
    issue(1); cp_commit();

    for (int lt = 0; lt < NLT; lt++) {
        float accS[2][4][4], accT[2][4][4];
        #pragma unroll
        for (int mt = 0; mt < 2; mt++)
            #pragma unroll
            for (int nt = 0; nt < 4; nt++)
                #pragma unroll
                for (int j = 0; j < 4; j++) { accS[mt][nt][j] = 0.f; accT[mt][nt][j] = 0.f; }

        for (int c = 0; c < NKC; c++) {
            const int g = lt * NKC + c;
            cp_wait<1>();
            __syncthreads();
            const int gi = g + 2;
            if (gi < NG) issue(gi);
            cp_commit();

            const uint32_t sb = sbase + (uint32_t)(g % NST) * STAGE;
            #pragma unroll
            for (int kk = 0; kk < 4; kk++) {
                uint32_t X[4][2], A0[2][4], A1[2][4];
                #pragma unroll
                for (int bt = 0; bt < 2; bt++)
                    ldm4(X[bt*2][0], X[bt*2][1], X[bt*2+1][0], X[bt*2+1][1], sb + OFF_X + offB[kk][bt]);
                #pragma unroll
                for (int mt = 0; mt < 2; mt++) {
                    ldm4(A0[mt][0], A0[mt][1], A0[mt][2], A0[mt][3], sb + OFF_U + offA[kk][mt]);
                    ldm4(A1[mt][0], A1[mt][1], A1[mt][2], A1[mt][3], sb + OFF_F + offA[kk][mt]);
                }
                #pragma unroll
                for (int mt = 0; mt < 2; mt++)
                    #pragma unroll
                    for (int nt = 0; nt < 4; nt++) {
                        MMA_F16(accS[mt][nt], A0[mt], X[nt]);
                        MMA_F16(accT[mt][nt], A1[mt], X[nt]);
                    }
            }
        }

        // max-free softmax partial update (scores bounded ~|2|)
        #pragma unroll
        for (int nt = 0; nt < 4; nt++)
            #pragma unroll
            for (int j = 0; j < 4; j++) {
                const int p = j & 1;
                const int l = lt * TN + wn * 32 + nt * 8 + tc * 2 + p;
                const bool v = (l < Ln);
                #pragma unroll
                for (int mt = 0; mt < 2; mt++) {
                    const int zi = mt * 2 + (j >> 1);
                    const float e = v ? __expf(accS[mt][nt][j]) : 0.f;
                    z[zi] += e;
                    nw[zi] = fmaf(e, accT[mt][nt][j], nw[zi]);
                }
            }
    }

    // ---- final reduction ----
    cp_wait<0>();
    __syncthreads();
    #pragma unroll
    for (int zi = 0; zi < 4; zi++) {
        z[zi]  += __shfl_xor_sync(0xffffffffu, z[zi], 1);
        z[zi]  += __shfl_xor_sync(0xffffffffu, z[zi], 2);
        nw[zi] += __shfl_xor_sync(0xffffffffu, nw[zi], 1);
        nw[zi] += __shfl_xor_sync(0xffffffffu, nw[zi], 2);
    }
    float2* red = (float2*)smem;   // [4 warp_n][64 rows]
    if (tc == 0) {
        #pragma unroll
        for (int zi = 0; zi < 4; zi++) {
            const int mt = zi >> 1, rh = zi & 1;
            const int row = wm * 32 + mt * 16 + rh * 8 + quad;
            red[wn * 64 + row] = make_float2(z[zi], nw[zi]);
        }
    }
    __syncthreads();
    if (tid < 64) {
        float zz = 0.f, nn = 0.f;
        #pragma unroll
        for (int w = 0; w < 4; w++) { float2 v = red[w * 64 + tid]; zz += v.x; nn += v.y; }
        const int y = yt * TM + tid;
        if (y < Yn) out[(size_t)b * Yn + y] = nn / zz + fb[y];
    }
}

// ---------------- host launch ----------------
extern "C" void kernel_launch(void* const* d_in, const int* in_sizes, int n_in,
                              void* d_out, int out_size) {
    const float* x  = (const float*)d_in[0];
    const float* Uw = (const float*)d_in[1];
    const float* Fw = (const float*)d_in[2];
    const float* fb = (const float*)d_in[3];
    float* out = (float*)d_out;
    (void)in_sizes; (void)n_in; (void)out_size;

    prep_all<<<4096, 256>>>(Uw, Fw, x);

    cudaFuncSetAttribute(attn_main, cudaFuncAttributeMaxDynamicSharedMemorySize, NST * STAGE);
    attn_main<<<dim3(YT, Bn), 256, NST * STAGE>>>(fb, out);
}